// round 1
// baseline (speedup 1.0000x reference)
#include <cuda_runtime.h>

#define SQn 512
#define Dn  256
#define ET  32      // e-tile width
#define SKG 8       // sk values per CTA
#define NT  512     // threads in main kernel

// Scratch (no allocations allowed -> __device__ globals)
__device__ float g_Kp[SQn * Dn];   // k = key + key@Wk + bk          [sk][d]
__device__ float g_Qt[Dn * SQn];   // q transposed                   [d][sq]
__device__ float g_Vp[SQn * Dn];   // v = value + value@Wva + bva    [sk][d]
__device__ float g_A [Dn * Dn];    // I + Wl                         [d][e]
__device__ float g_vs[SQn * Dn];   // value_sum accumulator          [sq][e]

// ---------------------------------------------------------------------------
// prep: A = I + Wl ; zero value_sum accumulator
// ---------------------------------------------------------------------------
__global__ void prep_kernel(const float* __restrict__ Wl) {
    int i = blockIdx.x * blockDim.x + threadIdx.x;
    if (i < Dn * Dn) {
        int d = i >> 8, e = i & 255;
        g_A[i] = Wl[i] + (d == e ? 1.0f : 0.0f);
    }
    if (i < SQn * Dn) g_vs[i] = 0.0f;
}

// ---------------------------------------------------------------------------
// resid: Y = X + X@W + b   (512x256 @ 256x256)
// dst: 0=g_Kp 1=g_Qt(transposed) 2=g_Vp 3=Yp(param)
// src_is_vs: read X from g_vs instead of param
// ---------------------------------------------------------------------------
template<bool TRANS>
__global__ void resid_kernel(const float* Xp, int src_is_vs,
                             const float* __restrict__ W,
                             const float* __restrict__ b,
                             float* Yp, int dst) {
    const float* X = src_is_vs ? (const float*)g_vs : Xp;
    float* Y = (dst == 0) ? g_Kp : (dst == 1) ? g_Qt : (dst == 2) ? g_Vp : Yp;

    __shared__ float Xs[8][Dn];
    const int tid = threadIdx.x;           // 256 threads, tid == output column e
    const int r0 = blockIdx.x * 8;         // 8 rows per block
    #pragma unroll
    for (int r = 0; r < 8; r++) Xs[r][tid] = X[(r0 + r) * Dn + tid];
    __syncthreads();

    float acc[8];
    const float bv = b[tid];
    #pragma unroll
    for (int r = 0; r < 8; r++) acc[r] = Xs[r][tid] + bv;   // residual + bias

    for (int d0 = 0; d0 < Dn; d0 += 4) {
        float w0 = W[(d0 + 0) * Dn + tid];
        float w1 = W[(d0 + 1) * Dn + tid];
        float w2 = W[(d0 + 2) * Dn + tid];
        float w3 = W[(d0 + 3) * Dn + tid];
        #pragma unroll
        for (int r = 0; r < 8; r++) {
            float4 xv = *reinterpret_cast<const float4*>(&Xs[r][d0]);
            acc[r] += xv.x * w0;
            acc[r] += xv.y * w1;
            acc[r] += xv.z * w2;
            acc[r] += xv.w * w3;
        }
    }
    #pragma unroll
    for (int r = 0; r < 8; r++) {
        if (TRANS) Y[tid * SQn + r0 + r] = acc[r];
        else       Y[(r0 + r) * Dn + tid] = acc[r];
    }
}

// ---------------------------------------------------------------------------
// main: for each sk:
//   L = Q @ (diag(k_sk) (I+Wl))[:, e-tile] + bl        (register-resident)
//   column-wise swishmax over sq (512 rows = 512 threads)
//   vsum[sq,e] += v[sk,e] * scale[sq,e]                (register-resident)
// then one atomicAdd per element into g_vs.
// ---------------------------------------------------------------------------
__global__ void __launch_bounds__(NT, 1)
attn_main_kernel(const float* __restrict__ bl) {
    __shared__ float Ws[Dn][ET];        // 32 KB: per-sk weight tile
    __shared__ float part[NT / 32][ET]; // cross-warp reduction partials
    __shared__ float gmax[ET];
    __shared__ float ginv[ET];
    __shared__ float vrow[ET];
    __shared__ float bls[ET];

    const int tid  = threadIdx.x;       // == sq row
    const int lane = tid & 31;
    const int wid  = tid >> 5;
    const int e0   = blockIdx.x * ET;
    const int sk0  = blockIdx.y * SKG;

    if (tid < ET) bls[tid] = bl[e0 + tid];

    float vsum[ET];
    #pragma unroll
    for (int e = 0; e < ET; e++) vsum[e] = 0.0f;

    for (int s = 0; s < SKG; s++) {
        const int sk = sk0 + s;
        __syncthreads();   // protect Ws/vrow/gmax/ginv from prior-iter readers

        // Build Ws[d][e] = k[sk,d] * (I+Wl)[d, e0+e]
        for (int idx = tid; idx < Dn * ET; idx += NT) {
            int d = idx >> 5, e = idx & (ET - 1);
            Ws[d][e] = g_Kp[sk * Dn + d] * g_A[d * Dn + e0 + e];
        }
        if (tid < ET) vrow[tid] = g_Vp[sk * Dn + e0 + tid];
        __syncthreads();

        // GEMM: L[tid, e] = bl[e] + sum_d q[tid,d] * Ws[d][e]
        float L[ET];
        #pragma unroll
        for (int e4 = 0; e4 < ET / 4; e4++) {
            float4 bv = *reinterpret_cast<const float4*>(&bls[e4 * 4]);
            L[e4*4+0] = bv.x; L[e4*4+1] = bv.y; L[e4*4+2] = bv.z; L[e4*4+3] = bv.w;
        }
        const float* qp = g_Qt + tid;   // Qt[d][sq], coalesced across threads
        for (int d0 = 0; d0 < Dn; d0 += 4) {
            float qa[4];
            #pragma unroll
            for (int j = 0; j < 4; j++) qa[j] = qp[(d0 + j) * SQn];
            #pragma unroll
            for (int j = 0; j < 4; j++) {
                #pragma unroll
                for (int e4 = 0; e4 < ET / 4; e4++) {
                    float4 wv = *reinterpret_cast<const float4*>(&Ws[d0 + j][e4 * 4]);
                    L[e4*4+0] += qa[j] * wv.x;
                    L[e4*4+1] += qa[j] * wv.y;
                    L[e4*4+2] += qa[j] * wv.z;
                    L[e4*4+3] += qa[j] * wv.w;
                }
            }
        }

        // Column max over the 512 sq rows (warp butterfly + cross-warp)
        #pragma unroll
        for (int e = 0; e < ET; e++) {
            float m = L[e];
            #pragma unroll
            for (int off = 16; off > 0; off >>= 1)
                m = fmaxf(m, __shfl_xor_sync(0xffffffffu, m, off));
            if (lane == e) part[wid][e] = m;
        }
        __syncthreads();
        if (tid < ET) {
            float m = part[0][tid];
            #pragma unroll
            for (int w = 1; w < NT / 32; w++) m = fmaxf(m, part[w][tid]);
            gmax[tid] = m;
        }
        __syncthreads();

        // xexp = x * exp(x - max)
        #pragma unroll
        for (int e = 0; e < ET; e++)
            L[e] = L[e] * __expf(L[e] - gmax[e]);

        // Column sum of |xexp|
        #pragma unroll
        for (int e = 0; e < ET; e++) {
            float sv = fabsf(L[e]);
            #pragma unroll
            for (int off = 16; off > 0; off >>= 1)
                sv += __shfl_xor_sync(0xffffffffu, sv, off);
            if (lane == e) part[wid][e] = sv;
        }
        __syncthreads();
        if (tid < ET) {
            float sv = part[0][tid];
            #pragma unroll
            for (int w = 1; w < NT / 32; w++) sv += part[w][tid];
            ginv[tid] = 1.0f / (sv + 1.0f);   // NOT_EPSILON = 1.0
        }
        __syncthreads();

        // vsum[sq,e] += v[sk,e] * xexp * (1/(sum+1))
        #pragma unroll
        for (int e = 0; e < ET; e++)
            vsum[e] += vrow[e] * L[e] * ginv[e];
    }

    float* vp = g_vs + tid * Dn + e0;
    #pragma unroll
    for (int e = 0; e < ET; e++) atomicAdd(vp + e, vsum[e]);
}

// ---------------------------------------------------------------------------
extern "C" void kernel_launch(void* const* d_in, const int* in_sizes, int n_in,
                              void* d_out, int out_size) {
    const float* query = (const float*)d_in[0];
    const float* key   = (const float*)d_in[1];
    const float* value = (const float*)d_in[2];
    const float* Wk    = (const float*)d_in[3];
    const float* bk    = (const float*)d_in[4];
    const float* Wq    = (const float*)d_in[5];
    const float* bq    = (const float*)d_in[6];
    const float* Wva   = (const float*)d_in[7];
    const float* bva   = (const float*)d_in[8];
    const float* Wl    = (const float*)d_in[9];
    const float* bl    = (const float*)d_in[10];
    const float* Wvo   = (const float*)d_in[11];
    const float* bvo   = (const float*)d_in[12];
    float* out = (float*)d_out;

    // A = I + Wl ; zero value_sum
    prep_kernel<<<512, 256>>>(Wl);
    // k = key + key@Wk + bk           -> g_Kp
    resid_kernel<false><<<64, 256>>>(key, 0, Wk, bk, nullptr, 0);
    // q = query + query@Wq + bq       -> g_Qt (transposed [d][sq])
    resid_kernel<true ><<<64, 256>>>(query, 0, Wq, bq, nullptr, 1);
    // v = value + value@Wva + bva     -> g_Vp
    resid_kernel<false><<<64, 256>>>(value, 0, Wva, bva, nullptr, 2);
    // fused logits GEMM + swishmax + key-axis reduction -> g_vs
    attn_main_kernel<<<dim3(Dn / ET, SQn / SKG), NT>>>(bl);
    // value_out = vs + vs@Wvo + bvo   -> d_out
    resid_kernel<false><<<64, 256>>>(nullptr, 1, Wvo, bvo, out, 3);
}

// round 2
// speedup vs baseline: 1.0054x; 1.0054x over previous
#include <cuda_runtime.h>

#define SQn 512
#define Dn  256
#define ET  32      // e-tile width
#define SKG 8       // sk values per CTA
#define NT  512     // threads in main kernel

// Scratch (no allocations allowed -> __device__ globals)
__device__ float g_Kp[SQn * Dn];   // k = key + key@Wk + bk          [sk][d]
__device__ float g_Qt[Dn * SQn];   // q transposed                   [d][sq]
__device__ float g_Vp[SQn * Dn];   // v = value + value@Wva + bva    [sk][d]
__device__ float g_A [Dn * Dn];    // I + Wl                         [d][e]
__device__ float g_vs[SQn * Dn];   // value_sum accumulator          [sq][e]

// ---------------------------------------------------------------------------
// prep: A = I + Wl ; zero value_sum accumulator
// ---------------------------------------------------------------------------
__global__ void prep_kernel(const float* __restrict__ Wl) {
    int i = blockIdx.x * blockDim.x + threadIdx.x;
    if (i < Dn * Dn) {
        int d = i >> 8, e = i & 255;
        g_A[i] = Wl[i] + (d == e ? 1.0f : 0.0f);
    }
    if (i < SQn * Dn) g_vs[i] = 0.0f;
}

// ---------------------------------------------------------------------------
// resid: Y = X + X@W + b   (512x256 @ 256x256)
// dst: 0=g_Kp 1=g_Qt(transposed) 2=g_Vp 3=Yp(param)
// src_is_vs: read X from g_vs instead of param
// ---------------------------------------------------------------------------
template<bool TRANS>
__global__ void resid_kernel(const float* Xp, int src_is_vs,
                             const float* __restrict__ W,
                             const float* __restrict__ b,
                             float* Yp, int dst) {
    const float* X = src_is_vs ? (const float*)g_vs : Xp;
    float* Y = (dst == 0) ? g_Kp : (dst == 1) ? g_Qt : (dst == 2) ? g_Vp : Yp;

    __shared__ float Xs[8][Dn];
    const int tid = threadIdx.x;           // 256 threads, tid == output column e
    const int r0 = blockIdx.x * 8;         // 8 rows per block
    #pragma unroll
    for (int r = 0; r < 8; r++) Xs[r][tid] = X[(r0 + r) * Dn + tid];
    __syncthreads();

    float acc[8];
    const float bv = b[tid];
    #pragma unroll
    for (int r = 0; r < 8; r++) acc[r] = Xs[r][tid] + bv;   // residual + bias

    for (int d0 = 0; d0 < Dn; d0 += 4) {
        float w0 = W[(d0 + 0) * Dn + tid];
        float w1 = W[(d0 + 1) * Dn + tid];
        float w2 = W[(d0 + 2) * Dn + tid];
        float w3 = W[(d0 + 3) * Dn + tid];
        #pragma unroll
        for (int r = 0; r < 8; r++) {
            float4 xv = *reinterpret_cast<const float4*>(&Xs[r][d0]);
            acc[r] += xv.x * w0;
            acc[r] += xv.y * w1;
            acc[r] += xv.z * w2;
            acc[r] += xv.w * w3;
        }
    }
    #pragma unroll
    for (int r = 0; r < 8; r++) {
        if (TRANS) Y[tid * SQn + r0 + r] = acc[r];
        else       Y[(r0 + r) * Dn + tid] = acc[r];
    }
}

// ---------------------------------------------------------------------------
// main: for each sk:
//   L = Q @ (diag(k_sk) (I+Wl))[:, e-tile] + bl        (register-resident)
//   column-wise swishmax over sq (512 rows = 512 threads)
//   vsum[sq,e] += v[sk,e] * scale[sq,e]                (register-resident)
// then one atomicAdd per element into g_vs.
// ---------------------------------------------------------------------------
__global__ void __launch_bounds__(NT, 1)
attn_main_kernel(const float* __restrict__ bl) {
    __shared__ float Ws[Dn][ET];        // 32 KB: per-sk weight tile
    __shared__ float part[NT / 32][ET]; // cross-warp reduction partials
    __shared__ float gmax[ET];
    __shared__ float ginv[ET];
    __shared__ float vrow[ET];
    __shared__ float bls[ET];

    const int tid  = threadIdx.x;       // == sq row
    const int lane = tid & 31;
    const int wid  = tid >> 5;
    const int e0   = blockIdx.x * ET;
    const int sk0  = blockIdx.y * SKG;

    if (tid < ET) bls[tid] = bl[e0 + tid];

    float vsum[ET];
    #pragma unroll
    for (int e = 0; e < ET; e++) vsum[e] = 0.0f;

    for (int s = 0; s < SKG; s++) {
        const int sk = sk0 + s;
        __syncthreads();   // protect Ws/vrow/gmax/ginv from prior-iter readers

        // Build Ws[d][e] = k[sk,d] * (I+Wl)[d, e0+e]
        for (int idx = tid; idx < Dn * ET; idx += NT) {
            int d = idx >> 5, e = idx & (ET - 1);
            Ws[d][e] = g_Kp[sk * Dn + d] * g_A[d * Dn + e0 + e];
        }
        if (tid < ET) vrow[tid] = g_Vp[sk * Dn + e0 + tid];
        __syncthreads();

        // GEMM: L[tid, e] = bl[e] + sum_d q[tid,d] * Ws[d][e]
        float L[ET];
        #pragma unroll
        for (int e4 = 0; e4 < ET / 4; e4++) {
            float4 bv = *reinterpret_cast<const float4*>(&bls[e4 * 4]);
            L[e4*4+0] = bv.x; L[e4*4+1] = bv.y; L[e4*4+2] = bv.z; L[e4*4+3] = bv.w;
        }
        const float* qp = g_Qt + tid;   // Qt[d][sq], coalesced across threads
        for (int d0 = 0; d0 < Dn; d0 += 4) {
            float qa[4];
            #pragma unroll
            for (int j = 0; j < 4; j++) qa[j] = qp[(d0 + j) * SQn];
            #pragma unroll
            for (int j = 0; j < 4; j++) {
                #pragma unroll
                for (int e4 = 0; e4 < ET / 4; e4++) {
                    float4 wv = *reinterpret_cast<const float4*>(&Ws[d0 + j][e4 * 4]);
                    L[e4*4+0] += qa[j] * wv.x;
                    L[e4*4+1] += qa[j] * wv.y;
                    L[e4*4+2] += qa[j] * wv.z;
                    L[e4*4+3] += qa[j] * wv.w;
                }
            }
        }

        // Column max over the 512 sq rows (warp butterfly + cross-warp)
        #pragma unroll
        for (int e = 0; e < ET; e++) {
            float m = L[e];
            #pragma unroll
            for (int off = 16; off > 0; off >>= 1)
                m = fmaxf(m, __shfl_xor_sync(0xffffffffu, m, off));
            if (lane == e) part[wid][e] = m;
        }
        __syncthreads();
        if (tid < ET) {
            float m = part[0][tid];
            #pragma unroll
            for (int w = 1; w < NT / 32; w++) m = fmaxf(m, part[w][tid]);
            gmax[tid] = m;
        }
        __syncthreads();

        // xexp = x * exp(x - max)
        #pragma unroll
        for (int e = 0; e < ET; e++)
            L[e] = L[e] * __expf(L[e] - gmax[e]);

        // Column sum of |xexp|
        #pragma unroll
        for (int e = 0; e < ET; e++) {
            float sv = fabsf(L[e]);
            #pragma unroll
            for (int off = 16; off > 0; off >>= 1)
                sv += __shfl_xor_sync(0xffffffffu, sv, off);
            if (lane == e) part[wid][e] = sv;
        }
        __syncthreads();
        if (tid < ET) {
            float sv = part[0][tid];
            #pragma unroll
            for (int w = 1; w < NT / 32; w++) sv += part[w][tid];
            ginv[tid] = 1.0f / (sv + 1.0f);   // NOT_EPSILON = 1.0
        }
        __syncthreads();

        // vsum[sq,e] += v[sk,e] * xexp * (1/(sum+1))
        #pragma unroll
        for (int e = 0; e < ET; e++)
            vsum[e] += vrow[e] * L[e] * ginv[e];
    }

    float* vp = g_vs + tid * Dn + e0;
    #pragma unroll
    for (int e = 0; e < ET; e++) atomicAdd(vp + e, vsum[e]);
}

// ---------------------------------------------------------------------------
extern "C" void kernel_launch(void* const* d_in, const int* in_sizes, int n_in,
                              void* d_out, int out_size) {
    const float* query = (const float*)d_in[0];
    const float* key   = (const float*)d_in[1];
    const float* value = (const float*)d_in[2];
    const float* Wk    = (const float*)d_in[3];
    const float* bk    = (const float*)d_in[4];
    const float* Wq    = (const float*)d_in[5];
    const float* bq    = (const float*)d_in[6];
    const float* Wva   = (const float*)d_in[7];
    const float* bva   = (const float*)d_in[8];
    const float* Wl    = (const float*)d_in[9];
    const float* bl    = (const float*)d_in[10];
    const float* Wvo   = (const float*)d_in[11];
    const float* bvo   = (const float*)d_in[12];
    float* out = (float*)d_out;

    // A = I + Wl ; zero value_sum
    prep_kernel<<<512, 256>>>(Wl);
    // k = key + key@Wk + bk           -> g_Kp
    resid_kernel<false><<<64, 256>>>(key, 0, Wk, bk, nullptr, 0);
    // q = query + query@Wq + bq       -> g_Qt (transposed [d][sq])
    resid_kernel<true ><<<64, 256>>>(query, 0, Wq, bq, nullptr, 1);
    // v = value + value@Wva + bva     -> g_Vp
    resid_kernel<false><<<64, 256>>>(value, 0, Wva, bva, nullptr, 2);
    // fused logits GEMM + swishmax + key-axis reduction -> g_vs
    attn_main_kernel<<<dim3(Dn / ET, SQn / SKG), NT>>>(bl);
    // value_out = vs + vs@Wvo + bvo   -> d_out
    resid_kernel<false><<<64, 256>>>(nullptr, 1, Wvo, bvo, out, 3);
}

// round 4
// speedup vs baseline: 3.5490x; 3.5301x over previous
#include <cuda_runtime.h>
#include <cuda_bf16.h>
#include <stdint.h>

#define SQ 512
#define DD 256

// ------------------- device scratch -------------------
__device__ float g_Kp[SQ*DD];                      // k = key + key@Wk + bk
__device__ float g_Vp[SQ*DD];                      // v = value + value@Wva + bva
__device__ float g_A [DD*DD];                      // A[d][e] = Wl[d][e] + (d==e)
__device__ float g_vs[SQ*DD];                      // value_sum accumulator
__device__ __align__(16) uint8_t g_Qhi[SQ*DD*2];   // q hi bf16, 4 k-chunks, SW128
__device__ __align__(16) uint8_t g_Qlo[SQ*DD*2];   // q lo bf16

#define SWZ(o) ((o) ^ (((o) >> 3) & 0x70))

// ------------------- helpers -------------------
__device__ __forceinline__ uint32_t smem_u32(const void* p) {
    uint32_t a;
    asm("{ .reg .u64 t; cvta.to.shared.u64 t, %1; cvt.u32.u64 %0, t; }" : "=r"(a) : "l"(p));
    return a;
}
__device__ __forceinline__ void ldsm_x4(uint32_t* r, uint32_t a) {
    asm volatile("ldmatrix.sync.aligned.m8n8.x4.shared.b16 {%0,%1,%2,%3}, [%4];"
        : "=r"(r[0]), "=r"(r[1]), "=r"(r[2]), "=r"(r[3]) : "r"(a));
}
__device__ __forceinline__ void ldsm_x4_t(uint32_t* r, uint32_t a) {
    asm volatile("ldmatrix.sync.aligned.m8n8.x4.trans.shared.b16 {%0,%1,%2,%3}, [%4];"
        : "=r"(r[0]), "=r"(r[1]), "=r"(r[2]), "=r"(r[3]) : "r"(a));
}
__device__ __forceinline__ void mma_bf16(float* c, const uint32_t* a, const uint32_t* b) {
    asm volatile("mma.sync.aligned.m16n8k16.row.col.f32.bf16.bf16.f32 "
        "{%0,%1,%2,%3}, {%4,%5,%6,%7}, {%8,%9}, {%0,%1,%2,%3};"
        : "+f"(c[0]), "+f"(c[1]), "+f"(c[2]), "+f"(c[3])
        : "r"(a[0]), "r"(a[1]), "r"(a[2]), "r"(a[3]), "r"(b[0]), "r"(b[1]));
}

// ------------------- smem layout (dynamic) -------------------
#define QB_O   0          // 65536 : Q chunk [512 m][64 k] bf16 SW128
#define BH_O   65536      // 32768 : Bt hi [256 k][64 n] bf16 SW128
#define BL_O   98304      // 32768 : Bt lo
#define PART_O 131072     // 4096  : [16 w][64 c]
#define GMX_O  135168     // 256
#define GINV_O 135424     // 256
#define VR_O   135680     // 256   : [2 skl][32 e]
#define SMEM_SZ 136192

// ------------------- prep: A = I + Wl ; zero vs -------------------
__global__ void prep_kernel(const float* __restrict__ Wl) {
    int i = blockIdx.x * 256 + threadIdx.x;
    if (i < DD * DD) {
        int d = i >> 8, e = i & 255;
        g_A[i] = Wl[i] + (d == e ? 1.0f : 0.0f);
    }
    if (i < SQ * DD) g_vs[i] = 0.0f;
}

// ------------------- fused residual for k/q/v -------------------
__global__ void resid3_kernel(const float* __restrict__ key, const float* __restrict__ query,
                              const float* __restrict__ value,
                              const float* __restrict__ Wk, const float* __restrict__ bk,
                              const float* __restrict__ Wq, const float* __restrict__ bq,
                              const float* __restrict__ Wva, const float* __restrict__ bva) {
    const int which = blockIdx.y;
    const float* X = which == 0 ? key : which == 1 ? query : value;
    const float* W = which == 0 ? Wk  : which == 1 ? Wq    : Wva;
    const float* b = which == 0 ? bk  : which == 1 ? bq    : bva;

    __shared__ float Xs[4][DD];
    const int tid = threadIdx.x;           // output column d
    const int r0 = blockIdx.x * 4;
    #pragma unroll
    for (int r = 0; r < 4; r++) Xs[r][tid] = X[(r0 + r) * DD + tid];
    __syncthreads();

    float acc[4];
    const float bv = b[tid];
    #pragma unroll
    for (int r = 0; r < 4; r++) acc[r] = Xs[r][tid] + bv;

    for (int d0 = 0; d0 < DD; d0 += 8) {
        float w[8];
        #pragma unroll
        for (int j = 0; j < 8; j++) w[j] = W[(d0 + j) * DD + tid];
        #pragma unroll
        for (int r = 0; r < 4; r++) {
            float4 x0 = *reinterpret_cast<const float4*>(&Xs[r][d0]);
            float4 x1 = *reinterpret_cast<const float4*>(&Xs[r][d0 + 4]);
            acc[r] += x0.x * w[0] + x0.y * w[1] + x0.z * w[2] + x0.w * w[3]
                    + x1.x * w[4] + x1.y * w[5] + x1.z * w[6] + x1.w * w[7];
        }
    }

    if (which == 0) {
        #pragma unroll
        for (int r = 0; r < 4; r++) g_Kp[(r0 + r) * DD + tid] = acc[r];
    } else if (which == 2) {
        #pragma unroll
        for (int r = 0; r < 4; r++) g_Vp[(r0 + r) * DD + tid] = acc[r];
    } else {
        // q: split hi/lo bf16, store per 64-wide k-chunk, SW128-swizzled
        #pragma unroll
        for (int r = 0; r < 4; r++) {
            int sq = r0 + r;
            int kc = tid >> 6, kr = tid & 63;
            uint32_t off = (uint32_t)kc * 65536u + SWZ((uint32_t)(sq * 128 + kr * 2));
            __nv_bfloat16 h = __float2bfloat16(acc[r]);
            float lo = acc[r] - __bfloat162float(h);
            *reinterpret_cast<__nv_bfloat16*>(g_Qhi + off) = h;
            *reinterpret_cast<__nv_bfloat16*>(g_Qlo + off) = __float2bfloat16(lo);
        }
    }
}

// ------------------- final residual: out = vs + vs@Wvo + bvo -------------------
__global__ void resid_out_kernel(const float* __restrict__ W, const float* __restrict__ b,
                                 float* __restrict__ Y) {
    __shared__ float Xs[4][DD];
    const int tid = threadIdx.x;
    const int r0 = blockIdx.x * 4;
    #pragma unroll
    for (int r = 0; r < 4; r++) Xs[r][tid] = g_vs[(r0 + r) * DD + tid];
    __syncthreads();
    float acc[4];
    const float bv = b[tid];
    #pragma unroll
    for (int r = 0; r < 4; r++) acc[r] = Xs[r][tid] + bv;
    for (int d0 = 0; d0 < DD; d0 += 8) {
        float w[8];
        #pragma unroll
        for (int j = 0; j < 8; j++) w[j] = W[(d0 + j) * DD + tid];
        #pragma unroll
        for (int r = 0; r < 4; r++) {
            float4 x0 = *reinterpret_cast<const float4*>(&Xs[r][d0]);
            float4 x1 = *reinterpret_cast<const float4*>(&Xs[r][d0 + 4]);
            acc[r] += x0.x * w[0] + x0.y * w[1] + x0.z * w[2] + x0.w * w[3]
                    + x1.x * w[4] + x1.y * w[5] + x1.z * w[6] + x1.w * w[7];
        }
    }
    #pragma unroll
    for (int r = 0; r < 4; r++) Y[(r0 + r) * DD + tid] = acc[r];
}

// ------------------- MMA pass: acc += Qchunk(kc) x Bt -------------------
__device__ __forceinline__ void mma_pass(float (*acc)[8][4], uint32_t qb, uint32_t bb,
                                         int kc, int L, int w) {
    #pragma unroll
    for (int ks = 0; ks < 4; ks++) {
        uint32_t af[2][4];
        #pragma unroll
        for (int mi = 0; mi < 2; mi++) {
            int row = w * 32 + mi * 16 + (L & 15);
            uint32_t off = (uint32_t)(row * 128) + ((uint32_t)((ks * 2 + (L >> 4)) * 16) ^ (uint32_t)((row & 7) * 16));
            ldsm_x4(af[mi], qb + off);
        }
        int brow = kc * 64 + ks * 16 + (L & 15);
        uint32_t bxor = (uint32_t)((brow & 7) * 16);
        #pragma unroll
        for (int h = 0; h < 2; h++) {
            uint32_t bf[8];
            #pragma unroll
            for (int qq = 0; qq < 2; qq++) {
                uint32_t unit = (uint32_t)(h * 4 + qq * 2 + (L >> 4));
                uint32_t off = (uint32_t)(brow * 128) + ((unit * 16) ^ bxor);
                ldsm_x4_t(bf + qq * 4, bb + off);
            }
            #pragma unroll
            for (int mi = 0; mi < 2; mi++)
                #pragma unroll
                for (int nj = 0; nj < 4; nj++)
                    mma_bf16(acc[mi][h * 4 + nj], af[mi], &bf[nj * 2]);
        }
    }
}

// ------------------- main fused kernel -------------------
__global__ void __launch_bounds__(512, 1)
attn_main_kernel(const float* __restrict__ bl) {
    extern __shared__ __align__(128) uint8_t sm[];
    const uint32_t smb = smem_u32(sm);
    const int tid = threadIdx.x, L = tid & 31, w = tid >> 5;
    const int e0 = blockIdx.x * 32, skb = blockIdx.y * 32;

    float* PART = (float*)(sm + PART_O);
    float* GMX  = (float*)(sm + GMX_O);
    float* GINV = (float*)(sm + GINV_O);
    float* VR   = (float*)(sm + VR_O);

    // per-thread bl values: slot j = e4*2+p -> e_local = e4*8 + (L&3)*2 + p
    float blv[8];
    #pragma unroll
    for (int j = 0; j < 8; j++)
        blv[j] = bl[e0 + (j >> 1) * 8 + (L & 3) * 2 + (j & 1)];

    float vs[32];
    #pragma unroll
    for (int i = 0; i < 32; i++) vs[i] = 0.0f;

    #pragma unroll 1
    for (int rnd = 0; rnd < 16; rnd++) {
        const int sk0 = skb + rnd * 2;
        __syncthreads();   // prior round's Bt/VR consumers done

        // ---- build Bt[d][n] hi/lo : n = skl*32 + e_local ----
        #pragma unroll
        for (int i = 0; i < 4; i++) {
            int u = tid + i * 512;
            int d = u >> 3, g = u & 7;
            int skl = g >> 2;
            const float4* ap = (const float4*)(g_A + d * DD + e0 + (g & 3) * 8);
            float kv = g_Kp[(sk0 + skl) * DD + d];
            float4 a0 = ap[0], a1 = ap[1];
            float p[8] = { kv*a0.x, kv*a0.y, kv*a0.z, kv*a0.w,
                           kv*a1.x, kv*a1.y, kv*a1.z, kv*a1.w };
            uint32_t H[4], Lo[4];
            #pragma unroll
            for (int j = 0; j < 4; j++) {
                __nv_bfloat16 h0 = __float2bfloat16(p[2*j]);
                __nv_bfloat16 h1 = __float2bfloat16(p[2*j+1]);
                __nv_bfloat16 l0 = __float2bfloat16(p[2*j]   - __bfloat162float(h0));
                __nv_bfloat16 l1 = __float2bfloat16(p[2*j+1] - __bfloat162float(h1));
                H[j]  = (uint32_t)__bfloat16_as_ushort(h0) | ((uint32_t)__bfloat16_as_ushort(h1) << 16);
                Lo[j] = (uint32_t)__bfloat16_as_ushort(l0) | ((uint32_t)__bfloat16_as_ushort(l1) << 16);
            }
            uint32_t off = (uint32_t)(d * 128 + ((g ^ (d & 7)) * 16));
            *(uint4*)(sm + BH_O + off) = make_uint4(H[0], H[1], H[2], H[3]);
            *(uint4*)(sm + BL_O + off) = make_uint4(Lo[0], Lo[1], Lo[2], Lo[3]);
        }
        if (tid < 64) VR[tid] = g_Vp[(sk0 + (tid >> 5)) * DD + e0 + (tid & 31)];

        float acc[2][8][4];
        #pragma unroll
        for (int mi = 0; mi < 2; mi++)
            #pragma unroll
            for (int ni = 0; ni < 8; ni++)
                #pragma unroll
                for (int c = 0; c < 4; c++) acc[mi][ni][c] = 0.0f;

        #pragma unroll 1
        for (int kc = 0; kc < 4; kc++) {
            __syncthreads();
            {   // Q hi chunk
                const uint4* s4 = (const uint4*)(g_Qhi + kc * 65536);
                uint4* d4 = (uint4*)(sm + QB_O);
                #pragma unroll
                for (int j = 0; j < 8; j++) d4[tid + j * 512] = s4[tid + j * 512];
            }
            __syncthreads();
            mma_pass(acc, smb + QB_O, smb + BH_O, kc, L, w);  // hi * Bhi
            mma_pass(acc, smb + QB_O, smb + BL_O, kc, L, w);  // hi * Blo
            __syncthreads();
            {   // Q lo chunk
                const uint4* s4 = (const uint4*)(g_Qlo + kc * 65536);
                uint4* d4 = (uint4*)(sm + QB_O);
                #pragma unroll
                for (int j = 0; j < 8; j++) d4[tid + j * 512] = s4[tid + j * 512];
            }
            __syncthreads();
            mma_pass(acc, smb + QB_O, smb + BH_O, kc, L, w);  // lo * Bhi
        }

        // ---- epilogue: + bl, column swishmax over sq, vsum ----
        #pragma unroll
        for (int mi = 0; mi < 2; mi++)
            #pragma unroll
            for (int ni = 0; ni < 8; ni++)
                #pragma unroll
                for (int p = 0; p < 2; p++) {
                    float bv = blv[(ni & 3) * 2 + p];
                    acc[mi][ni][p]     += bv;
                    acc[mi][ni][p + 2] += bv;
                }

        float cm[16];
        #pragma unroll
        for (int ni = 0; ni < 8; ni++)
            #pragma unroll
            for (int p = 0; p < 2; p++)
                cm[ni * 2 + p] = fmaxf(fmaxf(acc[0][ni][p], acc[0][ni][p + 2]),
                                       fmaxf(acc[1][ni][p], acc[1][ni][p + 2]));
        #pragma unroll
        for (int off = 4; off <= 16; off <<= 1)
            #pragma unroll
            for (int i = 0; i < 16; i++)
                cm[i] = fmaxf(cm[i], __shfl_xor_sync(0xffffffffu, cm[i], off));
        if (L < 4)
            #pragma unroll
            for (int i = 0; i < 16; i++)
                PART[w * 64 + (i >> 1) * 8 + L * 2 + (i & 1)] = cm[i];
        __syncthreads();
        if (tid < 64) {
            float m = PART[tid];
            #pragma unroll
            for (int w2 = 1; w2 < 16; w2++) m = fmaxf(m, PART[w2 * 64 + tid]);
            GMX[tid] = m;
        }
        __syncthreads();

        float gm[16];
        #pragma unroll
        for (int i = 0; i < 16; i++)
            gm[i] = GMX[(i >> 1) * 8 + (L & 3) * 2 + (i & 1)];
        #pragma unroll
        for (int mi = 0; mi < 2; mi++)
            #pragma unroll
            for (int ni = 0; ni < 8; ni++)
                #pragma unroll
                for (int p = 0; p < 2; p++) {
                    float g = gm[ni * 2 + p];
                    float a0 = acc[mi][ni][p],     a1 = acc[mi][ni][p + 2];
                    acc[mi][ni][p]     = a0 * __expf(a0 - g);
                    acc[mi][ni][p + 2] = a1 * __expf(a1 - g);
                }

        float cs[16];
        #pragma unroll
        for (int ni = 0; ni < 8; ni++)
            #pragma unroll
            for (int p = 0; p < 2; p++)
                cs[ni * 2 + p] = fabsf(acc[0][ni][p]) + fabsf(acc[0][ni][p + 2])
                               + fabsf(acc[1][ni][p]) + fabsf(acc[1][ni][p + 2]);
        #pragma unroll
        for (int off = 4; off <= 16; off <<= 1)
            #pragma unroll
            for (int i = 0; i < 16; i++)
                cs[i] += __shfl_xor_sync(0xffffffffu, cs[i], off);
        if (L < 4)
            #pragma unroll
            for (int i = 0; i < 16; i++)
                PART[w * 64 + (i >> 1) * 8 + L * 2 + (i & 1)] = cs[i];
        __syncthreads();
        if (tid < 64) {
            float s = PART[tid];
            #pragma unroll
            for (int w2 = 1; w2 < 16; w2++) s += PART[w2 * 64 + tid];
            GINV[tid] = 1.0f / (s + 1.0f);   // NOT_EPSILON = 1.0
        }
        __syncthreads();

        float gv[16];
        #pragma unroll
        for (int i = 0; i < 16; i++) {
            int c = (i >> 1) * 8 + (L & 3) * 2 + (i & 1);
            int eL = ((i >> 1) & 3) * 8 + (L & 3) * 2 + (i & 1);
            gv[i] = GINV[c] * VR[(i >= 8 ? 32 : 0) + eL];
        }
        #pragma unroll
        for (int mi = 0; mi < 2; mi++)
            #pragma unroll
            for (int ni = 0; ni < 8; ni++)
                #pragma unroll
                for (int p = 0; p < 2; p++) {
                    float f = gv[ni * 2 + p];
                    int j = (ni & 3) * 2 + p;
                    vs[(mi * 2 + 0) * 8 + j] += acc[mi][ni][p]     * f;
                    vs[(mi * 2 + 1) * 8 + j] += acc[mi][ni][p + 2] * f;
                }
    }

    // ---- write vsum (accumulate across 16 sk-group CTAs) ----
    #pragma unroll
    for (int mi = 0; mi < 2; mi++)
        #pragma unroll
        for (int rh = 0; rh < 2; rh++)
            #pragma unroll
            for (int j = 0; j < 8; j++) {
                int m = w * 32 + mi * 16 + rh * 8 + (L >> 2);
                int e = e0 + (j >> 1) * 8 + (L & 3) * 2 + (j & 1);
                atomicAdd(&g_vs[m * DD + e], vs[(mi * 2 + rh) * 8 + j]);
            }
}

// ---------------------------------------------------------------------------
extern "C" void kernel_launch(void* const* d_in, const int* in_sizes, int n_in,
                              void* d_out, int out_size) {
    const float* query = (const float*)d_in[0];
    const float* key   = (const float*)d_in[1];
    const float* value = (const float*)d_in[2];
    const float* Wk    = (const float*)d_in[3];
    const float* bk    = (const float*)d_in[4];
    const float* Wq    = (const float*)d_in[5];
    const float* bq    = (const float*)d_in[6];
    const float* Wva   = (const float*)d_in[7];
    const float* bva   = (const float*)d_in[8];
    const float* Wl    = (const float*)d_in[9];
    const float* bl    = (const float*)d_in[10];
    const float* Wvo   = (const float*)d_in[11];
    const float* bvo   = (const float*)d_in[12];
    float* out = (float*)d_out;

    cudaFuncSetAttribute(attn_main_kernel, cudaFuncAttributeMaxDynamicSharedMemorySize, SMEM_SZ);

    prep_kernel<<<512, 256>>>(Wl);
    resid3_kernel<<<dim3(128, 3), 256>>>(key, query, value, Wk, bk, Wq, bq, Wva, bva);
    attn_main_kernel<<<dim3(8, 16), 512, SMEM_SZ>>>(bl);
    resid_out_kernel<<<128, 256>>>(Wvo, bvo, out);
}

// round 5
// speedup vs baseline: 3.9523x; 1.1136x over previous
#include <cuda_runtime.h>
#include <cuda_bf16.h>
#include <stdint.h>

#define SQ 512
#define DD 256

// ------------------- device scratch -------------------
__device__ float g_Kp[SQ*DD];                      // k = key + key@Wk + bk
__device__ float g_Vp[SQ*DD];                      // v = value + value@Wva + bva
__device__ float g_A [DD*DD];                      // A[d][e] = Wl[d][e] + (d==e)
__device__ float g_vs[SQ*DD];                      // value_sum accumulator
__device__ __align__(16) uint8_t g_Qhi[SQ*DD*2];   // q hi bf16, 4 k-chunks, SW128
__device__ __align__(16) uint8_t g_Qlo[SQ*DD*2];   // q lo bf16

#define SWZ(o) ((o) ^ (((o) >> 3) & 0x70))

// ------------------- helpers -------------------
__device__ __forceinline__ uint32_t smem_u32(const void* p) {
    uint32_t a;
    asm("{ .reg .u64 t; cvta.to.shared.u64 t, %1; cvt.u32.u64 %0, t; }" : "=r"(a) : "l"(p));
    return a;
}
__device__ __forceinline__ void ldsm_x4(uint32_t* r, uint32_t a) {
    asm volatile("ldmatrix.sync.aligned.m8n8.x4.shared.b16 {%0,%1,%2,%3}, [%4];"
        : "=r"(r[0]), "=r"(r[1]), "=r"(r[2]), "=r"(r[3]) : "r"(a));
}
__device__ __forceinline__ void ldsm_x4_t(uint32_t* r, uint32_t a) {
    asm volatile("ldmatrix.sync.aligned.m8n8.x4.trans.shared.b16 {%0,%1,%2,%3}, [%4];"
        : "=r"(r[0]), "=r"(r[1]), "=r"(r[2]), "=r"(r[3]) : "r"(a));
}
__device__ __forceinline__ void mma_bf16(float* c, const uint32_t* a, const uint32_t* b) {
    asm volatile("mma.sync.aligned.m16n8k16.row.col.f32.bf16.bf16.f32 "
        "{%0,%1,%2,%3}, {%4,%5,%6,%7}, {%8,%9}, {%0,%1,%2,%3};"
        : "+f"(c[0]), "+f"(c[1]), "+f"(c[2]), "+f"(c[3])
        : "r"(a[0]), "r"(a[1]), "r"(a[2]), "r"(a[3]), "r"(b[0]), "r"(b[1]));
}
__device__ __forceinline__ void cpa16(uint32_t dst, const void* src) {
    asm volatile("cp.async.cg.shared.global [%0], [%1], 16;" :: "r"(dst), "l"(src));
}
#define CPA_COMMIT() asm volatile("cp.async.commit_group;" ::: "memory")
#define CPA_WAIT(n)  asm volatile("cp.async.wait_group %0;" :: "n"(n) : "memory")

// ------------------- smem layout (dynamic) -------------------
#define QB0_O  0          // 65536 : Q chunk buffer 0
#define QB1_O  65536      // 65536 : Q chunk buffer 1
#define BH_O   131072     // 32768 : Bt hi [256 k][64 n] bf16 SW128
#define BL_O   163840     // 32768 : Bt lo
#define PART_O 196608     // 4096  : [16 w][64 c]
#define GMX_O  200704     // 256
#define GINV_O 200960     // 256
#define VR_O   201216     // 256   : [2 skl][32 e]
#define SMEM_SZ 201728

// ------------------- prep: A = I + Wl ; zero vs -------------------
__global__ void prep_kernel(const float* __restrict__ Wl) {
    int i = blockIdx.x * 256 + threadIdx.x;
    if (i < DD * DD) {
        int d = i >> 8, e = i & 255;
        g_A[i] = Wl[i] + (d == e ? 1.0f : 0.0f);
    }
    if (i < SQ * DD) g_vs[i] = 0.0f;
}

// ------------------- fused residual for k/q/v (2 rows/CTA) -------------------
__global__ void resid3_kernel(const float* __restrict__ key, const float* __restrict__ query,
                              const float* __restrict__ value,
                              const float* __restrict__ Wk, const float* __restrict__ bk,
                              const float* __restrict__ Wq, const float* __restrict__ bq,
                              const float* __restrict__ Wva, const float* __restrict__ bva) {
    const int which = blockIdx.y;
    const float* X = which == 0 ? key : which == 1 ? query : value;
    const float* W = which == 0 ? Wk  : which == 1 ? Wq    : Wva;
    const float* b = which == 0 ? bk  : which == 1 ? bq    : bva;

    __shared__ float Xs[2][DD];
    const int tid = threadIdx.x;           // output column d
    const int r0 = blockIdx.x * 2;
    #pragma unroll
    for (int r = 0; r < 2; r++) Xs[r][tid] = X[(r0 + r) * DD + tid];
    __syncthreads();

    float acc[2];
    const float bv = b[tid];
    #pragma unroll
    for (int r = 0; r < 2; r++) acc[r] = Xs[r][tid] + bv;

    for (int d0 = 0; d0 < DD; d0 += 8) {
        float w[8];
        #pragma unroll
        for (int j = 0; j < 8; j++) w[j] = W[(d0 + j) * DD + tid];
        #pragma unroll
        for (int r = 0; r < 2; r++) {
            float4 x0 = *reinterpret_cast<const float4*>(&Xs[r][d0]);
            float4 x1 = *reinterpret_cast<const float4*>(&Xs[r][d0 + 4]);
            acc[r] += x0.x * w[0] + x0.y * w[1] + x0.z * w[2] + x0.w * w[3]
                    + x1.x * w[4] + x1.y * w[5] + x1.z * w[6] + x1.w * w[7];
        }
    }

    if (which == 0) {
        #pragma unroll
        for (int r = 0; r < 2; r++) g_Kp[(r0 + r) * DD + tid] = acc[r];
    } else if (which == 2) {
        #pragma unroll
        for (int r = 0; r < 2; r++) g_Vp[(r0 + r) * DD + tid] = acc[r];
    } else {
        #pragma unroll
        for (int r = 0; r < 2; r++) {
            int sq = r0 + r;
            int kc = tid >> 6, kr = tid & 63;
            uint32_t off = (uint32_t)kc * 65536u + SWZ((uint32_t)(sq * 128 + kr * 2));
            __nv_bfloat16 h = __float2bfloat16(acc[r]);
            float lo = acc[r] - __bfloat162float(h);
            *reinterpret_cast<__nv_bfloat16*>(g_Qhi + off) = h;
            *reinterpret_cast<__nv_bfloat16*>(g_Qlo + off) = __float2bfloat16(lo);
        }
    }
}

// ------------------- final residual: out = vs + vs@Wvo + bvo -------------------
__global__ void resid_out_kernel(const float* __restrict__ W, const float* __restrict__ b,
                                 float* __restrict__ Y) {
    __shared__ float Xs[2][DD];
    const int tid = threadIdx.x;
    const int r0 = blockIdx.x * 2;
    #pragma unroll
    for (int r = 0; r < 2; r++) Xs[r][tid] = g_vs[(r0 + r) * DD + tid];
    __syncthreads();
    float acc[2];
    const float bv = b[tid];
    #pragma unroll
    for (int r = 0; r < 2; r++) acc[r] = Xs[r][tid] + bv;
    for (int d0 = 0; d0 < DD; d0 += 8) {
        float w[8];
        #pragma unroll
        for (int j = 0; j < 8; j++) w[j] = W[(d0 + j) * DD + tid];
        #pragma unroll
        for (int r = 0; r < 2; r++) {
            float4 x0 = *reinterpret_cast<const float4*>(&Xs[r][d0]);
            float4 x1 = *reinterpret_cast<const float4*>(&Xs[r][d0 + 4]);
            acc[r] += x0.x * w[0] + x0.y * w[1] + x0.z * w[2] + x0.w * w[3]
                    + x1.x * w[4] + x1.y * w[5] + x1.z * w[6] + x1.w * w[7];
        }
    }
    #pragma unroll
    for (int r = 0; r < 2; r++) Y[(r0 + r) * DD + tid] = acc[r];
}

// ------------------- MMA passes -------------------
// hi chunk: A fragments loaded once, applied to both BH and BL
__device__ __forceinline__ void mma_hi(float (*acc)[8][4], uint32_t qb, uint32_t bh,
                                       uint32_t bl2, int kc, int L, int w) {
    #pragma unroll
    for (int ks = 0; ks < 4; ks++) {
        uint32_t af[2][4];
        #pragma unroll
        for (int mi = 0; mi < 2; mi++) {
            int row = w * 32 + mi * 16 + (L & 15);
            uint32_t off = (uint32_t)(row * 128) + ((uint32_t)((ks * 2 + (L >> 4)) * 16) ^ (uint32_t)((row & 7) * 16));
            ldsm_x4(af[mi], qb + off);
        }
        int brow = kc * 64 + ks * 16 + (L & 15);
        uint32_t bxor = (uint32_t)((brow & 7) * 16);
        #pragma unroll
        for (int h = 0; h < 2; h++) {
            uint32_t bf[8];
            #pragma unroll
            for (int qq = 0; qq < 2; qq++) {
                uint32_t unit = (uint32_t)(h * 4 + qq * 2 + (L >> 4));
                ldsm_x4_t(bf + qq * 4, bh + (uint32_t)(brow * 128) + ((unit * 16) ^ bxor));
            }
            #pragma unroll
            for (int mi = 0; mi < 2; mi++)
                #pragma unroll
                for (int nj = 0; nj < 4; nj++)
                    mma_bf16(acc[mi][h * 4 + nj], af[mi], &bf[nj * 2]);
            #pragma unroll
            for (int qq = 0; qq < 2; qq++) {
                uint32_t unit = (uint32_t)(h * 4 + qq * 2 + (L >> 4));
                ldsm_x4_t(bf + qq * 4, bl2 + (uint32_t)(brow * 128) + ((unit * 16) ^ bxor));
            }
            #pragma unroll
            for (int mi = 0; mi < 2; mi++)
                #pragma unroll
                for (int nj = 0; nj < 4; nj++)
                    mma_bf16(acc[mi][h * 4 + nj], af[mi], &bf[nj * 2]);
        }
    }
}
// lo chunk: single pass vs BH
__device__ __forceinline__ void mma_lo(float (*acc)[8][4], uint32_t qb, uint32_t bh,
                                       int kc, int L, int w) {
    #pragma unroll
    for (int ks = 0; ks < 4; ks++) {
        uint32_t af[2][4];
        #pragma unroll
        for (int mi = 0; mi < 2; mi++) {
            int row = w * 32 + mi * 16 + (L & 15);
            uint32_t off = (uint32_t)(row * 128) + ((uint32_t)((ks * 2 + (L >> 4)) * 16) ^ (uint32_t)((row & 7) * 16));
            ldsm_x4(af[mi], qb + off);
        }
        int brow = kc * 64 + ks * 16 + (L & 15);
        uint32_t bxor = (uint32_t)((brow & 7) * 16);
        #pragma unroll
        for (int h = 0; h < 2; h++) {
            uint32_t bf[8];
            #pragma unroll
            for (int qq = 0; qq < 2; qq++) {
                uint32_t unit = (uint32_t)(h * 4 + qq * 2 + (L >> 4));
                ldsm_x4_t(bf + qq * 4, bh + (uint32_t)(brow * 128) + ((unit * 16) ^ bxor));
            }
            #pragma unroll
            for (int mi = 0; mi < 2; mi++)
                #pragma unroll
                for (int nj = 0; nj < 4; nj++)
                    mma_bf16(acc[mi][h * 4 + nj], af[mi], &bf[nj * 2]);
        }
    }
}

// ------------------- main fused kernel -------------------
__global__ void __launch_bounds__(512, 1)
attn_main_kernel(const float* __restrict__ bl) {
    extern __shared__ __align__(128) uint8_t sm[];
    const uint32_t smb = smem_u32(sm);
    const int tid = threadIdx.x, L = tid & 31, w = tid >> 5;
    const int e0 = blockIdx.x * 32, skb = blockIdx.y * 32;

    float* PART = (float*)(sm + PART_O);
    float* GMX  = (float*)(sm + GMX_O);
    float* GINV = (float*)(sm + GINV_O);
    float* VR   = (float*)(sm + VR_O);

    float blv[8];
    #pragma unroll
    for (int j = 0; j < 8; j++)
        blv[j] = bl[e0 + (j >> 1) * 8 + (L & 3) * 2 + (j & 1)];

    float vs[32];
    #pragma unroll
    for (int i = 0; i < 32; i++) vs[i] = 0.0f;

    // chunk c (0..7): kc = c>>1, hi if (c&1)==0.  buffer = c&1 of {QB0,QB1}? No:
    // buffers alternate by chunk parity: chunk c -> buf[c&1].
    const uint32_t bufo[2] = { QB0_O, QB1_O };
    // prologue: prefetch chunk0 -> buf0, chunk1 -> buf1
    #pragma unroll
    for (int c = 0; c < 2; c++) {
        const uint8_t* src = (c & 1 ? g_Qlo : g_Qhi) + (c >> 1) * 65536;
        uint32_t dst = smb + bufo[c & 1];
        #pragma unroll
        for (int j = 0; j < 8; j++) {
            uint32_t off = (uint32_t)(tid + j * 512) * 16u;
            cpa16(dst + off, src + off);
        }
        CPA_COMMIT();
    }

    #pragma unroll 1
    for (int rnd = 0; rnd < 16; rnd++) {
        const int sk0 = skb + rnd * 2;
        __syncthreads();   // prior round's BH/BL/VR consumers done

        // ---- build Bt[d][n] hi/lo : n = skl*32 + e_local (overlaps in-flight cp.async) ----
        #pragma unroll
        for (int i = 0; i < 4; i++) {
            int u = tid + i * 512;
            int d = u >> 3, g = u & 7;
            int skl = g >> 2;
            const float4* ap = (const float4*)(g_A + d * DD + e0 + (g & 3) * 8);
            float kv = g_Kp[(sk0 + skl) * DD + d];
            float4 a0 = ap[0], a1 = ap[1];
            float p[8] = { kv*a0.x, kv*a0.y, kv*a0.z, kv*a0.w,
                           kv*a1.x, kv*a1.y, kv*a1.z, kv*a1.w };
            uint32_t H[4], Lo[4];
            #pragma unroll
            for (int j = 0; j < 4; j++) {
                __nv_bfloat16 h0 = __float2bfloat16(p[2*j]);
                __nv_bfloat16 h1 = __float2bfloat16(p[2*j+1]);
                __nv_bfloat16 l0 = __float2bfloat16(p[2*j]   - __bfloat162float(h0));
                __nv_bfloat16 l1 = __float2bfloat16(p[2*j+1] - __bfloat162float(h1));
                H[j]  = (uint32_t)__bfloat16_as_ushort(h0) | ((uint32_t)__bfloat16_as_ushort(h1) << 16);
                Lo[j] = (uint32_t)__bfloat16_as_ushort(l0) | ((uint32_t)__bfloat16_as_ushort(l1) << 16);
            }
            uint32_t off = (uint32_t)(d * 128 + ((g ^ (d & 7)) * 16));
            *(uint4*)(sm + BH_O + off) = make_uint4(H[0], H[1], H[2], H[3]);
            *(uint4*)(sm + BL_O + off) = make_uint4(Lo[0], Lo[1], Lo[2], Lo[3]);
        }
        if (tid < 64) VR[tid] = g_Vp[(sk0 + (tid >> 5)) * DD + e0 + (tid & 31)];

        float acc[2][8][4];
        #pragma unroll
        for (int mi = 0; mi < 2; mi++)
            #pragma unroll
            for (int ni = 0; ni < 8; ni++)
                #pragma unroll
                for (int c = 0; c < 4; c++) acc[mi][ni][c] = 0.0f;

        // ---- pipelined chunk loop ----
        #pragma unroll 1
        for (int c = 0; c < 8; c++) {
            if (rnd == 15 && c == 7) { CPA_WAIT(0); } else { CPA_WAIT(1); }
            __syncthreads();   // chunk c visible to all threads (incl. B tiles on c==0)

            uint32_t qb = smb + bufo[c & 1];
            int kc = c >> 1;
            if ((c & 1) == 0) mma_hi(acc, qb, smb + BH_O, smb + BL_O, kc, L, w);
            else              mma_lo(acc, qb, smb + BH_O, kc, L, w);

            __syncthreads();   // all warps done with buf[c&1] before re-fill

            if (!(rnd == 15 && c >= 6)) {
                int cn = (c + 2) & 7;   // next round wraps to same data
                const uint8_t* src = (cn & 1 ? g_Qlo : g_Qhi) + (cn >> 1) * 65536;
                uint32_t dst = smb + bufo[cn & 1];
                #pragma unroll
                for (int j = 0; j < 8; j++) {
                    uint32_t off = (uint32_t)(tid + j * 512) * 16u;
                    cpa16(dst + off, src + off);
                }
                CPA_COMMIT();
            }
        }

        // ---- epilogue: + bl, column swishmax over sq, vsum ----
        #pragma unroll
        for (int mi = 0; mi < 2; mi++)
            #pragma unroll
            for (int ni = 0; ni < 8; ni++)
                #pragma unroll
                for (int p = 0; p < 2; p++) {
                    float bv = blv[(ni & 3) * 2 + p];
                    acc[mi][ni][p]     += bv;
                    acc[mi][ni][p + 2] += bv;
                }

        float cm[16];
        #pragma unroll
        for (int ni = 0; ni < 8; ni++)
            #pragma unroll
            for (int p = 0; p < 2; p++)
                cm[ni * 2 + p] = fmaxf(fmaxf(acc[0][ni][p], acc[0][ni][p + 2]),
                                       fmaxf(acc[1][ni][p], acc[1][ni][p + 2]));
        #pragma unroll
        for (int off = 4; off <= 16; off <<= 1)
            #pragma unroll
            for (int i = 0; i < 16; i++)
                cm[i] = fmaxf(cm[i], __shfl_xor_sync(0xffffffffu, cm[i], off));
        if (L < 4)
            #pragma unroll
            for (int i = 0; i < 16; i++)
                PART[w * 64 + (i >> 1) * 8 + L * 2 + (i & 1)] = cm[i];
        __syncthreads();
        if (tid < 64) {
            float m = PART[tid];
            #pragma unroll
            for (int w2 = 1; w2 < 16; w2++) m = fmaxf(m, PART[w2 * 64 + tid]);
            GMX[tid] = m;
        }
        __syncthreads();

        float gm[16];
        #pragma unroll
        for (int i = 0; i < 16; i++)
            gm[i] = GMX[(i >> 1) * 8 + (L & 3) * 2 + (i & 1)];
        #pragma unroll
        for (int mi = 0; mi < 2; mi++)
            #pragma unroll
            for (int ni = 0; ni < 8; ni++)
                #pragma unroll
                for (int p = 0; p < 2; p++) {
                    float g = gm[ni * 2 + p];
                    float a0 = acc[mi][ni][p],     a1 = acc[mi][ni][p + 2];
                    acc[mi][ni][p]     = a0 * __expf(a0 - g);
                    acc[mi][ni][p + 2] = a1 * __expf(a1 - g);
                }

        float cs[16];
        #pragma unroll
        for (int ni = 0; ni < 8; ni++)
            #pragma unroll
            for (int p = 0; p < 2; p++)
                cs[ni * 2 + p] = fabsf(acc[0][ni][p]) + fabsf(acc[0][ni][p + 2])
                               + fabsf(acc[1][ni][p]) + fabsf(acc[1][ni][p + 2]);
        #pragma unroll
        for (int off = 4; off <= 16; off <<= 1)
            #pragma unroll
            for (int i = 0; i < 16; i++)
                cs[i] += __shfl_xor_sync(0xffffffffu, cs[i], off);
        if (L < 4)
            #pragma unroll
            for (int i = 0; i < 16; i++)
                PART[w * 64 + (i >> 1) * 8 + L * 2 + (i & 1)] = cs[i];
        __syncthreads();
        if (tid < 64) {
            float s = PART[tid];
            #pragma unroll
            for (int w2 = 1; w2 < 16; w2++) s += PART[w2 * 64 + tid];
            GINV[tid] = 1.0f / (s + 1.0f);   // NOT_EPSILON = 1.0
        }
        __syncthreads();

        float gv[16];
        #pragma unroll
        for (int i = 0; i < 16; i++) {
            int cidx = (i >> 1) * 8 + (L & 3) * 2 + (i & 1);
            int eL = ((i >> 1) & 3) * 8 + (L & 3) * 2 + (i & 1);
            gv[i] = GINV[cidx] * VR[(i >= 8 ? 32 : 0) + eL];
        }
        #pragma unroll
        for (int mi = 0; mi < 2; mi++)
            #pragma unroll
            for (int ni = 0; ni < 8; ni++)
                #pragma unroll
                for (int p = 0; p < 2; p++) {
                    float f = gv[ni * 2 + p];
                    int j = (ni & 3) * 2 + p;
                    vs[(mi * 2 + 0) * 8 + j] += acc[mi][ni][p]     * f;
                    vs[(mi * 2 + 1) * 8 + j] += acc[mi][ni][p + 2] * f;
                }
    }

    // ---- write vsum (accumulate across 16 sk-group CTAs) ----
    #pragma unroll
    for (int mi = 0; mi < 2; mi++)
        #pragma unroll
        for (int rh = 0; rh < 2; rh++)
            #pragma unroll
            for (int j = 0; j < 8; j++) {
                int m = w * 32 + mi * 16 + rh * 8 + (L >> 2);
                int e = e0 + (j >> 1) * 8 + (L & 3) * 2 + (j & 1);
                atomicAdd(&g_vs[m * DD + e], vs[(mi * 2 + rh) * 8 + j]);
            }
}

// ---------------------------------------------------------------------------
extern "C" void kernel_launch(void* const* d_in, const int* in_sizes, int n_in,
                              void* d_out, int out_size) {
    const float* query = (const float*)d_in[0];
    const float* key   = (const float*)d_in[1];
    const float* value = (const float*)d_in[2];
    const float* Wk    = (const float*)d_in[3];
    const float* bk    = (const float*)d_in[4];
    const float* Wq    = (const float*)d_in[5];
    const float* bq    = (const float*)d_in[6];
    const float* Wva   = (const float*)d_in[7];
    const float* bva   = (const float*)d_in[8];
    const float* Wl    = (const float*)d_in[9];
    const float* bl    = (const float*)d_in[10];
    const float* Wvo   = (const float*)d_in[11];
    const float* bvo   = (const float*)d_in[12];
    float* out = (float*)d_out;

    cudaFuncSetAttribute(attn_main_kernel, cudaFuncAttributeMaxDynamicSharedMemorySize, SMEM_SZ);

    prep_kernel<<<512, 256>>>(Wl);
    resid3_kernel<<<dim3(256, 3), 256>>>(key, query, value, Wk, bk, Wq, bq, Wva, bva);
    attn_main_kernel<<<dim3(8, 16), 512, SMEM_SZ>>>(bl);
    resid_out_kernel<<<256, 256>>>(Wvo, bvo, out);
}

// round 6
// speedup vs baseline: 4.4437x; 1.1243x over previous
#include <cuda_runtime.h>
#include <cuda_bf16.h>
#include <stdint.h>

#define SQ 512
#define DD 256

// ------------------- device scratch -------------------
__device__ float g_Kp[SQ*DD];                      // k = key + key@Wk + bk
__device__ float g_Vp[SQ*DD];                      // v = value + value@Wva + bva
__device__ float g_A [DD*DD];                      // A[d][e] = Wl[d][e] + (d==e)
__device__ float g_vs[SQ*DD];                      // value_sum accumulator
__device__ __align__(16) uint8_t g_Qhi[SQ*DD*2];   // q hi bf16, 4 k-chunks, SW128
__device__ __align__(16) uint8_t g_Qlo[SQ*DD*2];   // q lo bf16

#define SWZ(o) ((o) ^ (((o) >> 3) & 0x70))

// ------------------- helpers -------------------
__device__ __forceinline__ uint32_t smem_u32(const void* p) {
    uint32_t a;
    asm("{ .reg .u64 t; cvta.to.shared.u64 t, %1; cvt.u32.u64 %0, t; }" : "=r"(a) : "l"(p));
    return a;
}
__device__ __forceinline__ void ldsm_x4(uint32_t* r, uint32_t a) {
    asm volatile("ldmatrix.sync.aligned.m8n8.x4.shared.b16 {%0,%1,%2,%3}, [%4];"
        : "=r"(r[0]), "=r"(r[1]), "=r"(r[2]), "=r"(r[3]) : "r"(a));
}
__device__ __forceinline__ void ldsm_x4_t(uint32_t* r, uint32_t a) {
    asm volatile("ldmatrix.sync.aligned.m8n8.x4.trans.shared.b16 {%0,%1,%2,%3}, [%4];"
        : "=r"(r[0]), "=r"(r[1]), "=r"(r[2]), "=r"(r[3]) : "r"(a));
}
__device__ __forceinline__ void mma_bf16(float* c, const uint32_t* a, const uint32_t* b) {
    asm volatile("mma.sync.aligned.m16n8k16.row.col.f32.bf16.bf16.f32 "
        "{%0,%1,%2,%3}, {%4,%5,%6,%7}, {%8,%9}, {%0,%1,%2,%3};"
        : "+f"(c[0]), "+f"(c[1]), "+f"(c[2]), "+f"(c[3])
        : "r"(a[0]), "r"(a[1]), "r"(a[2]), "r"(a[3]), "r"(b[0]), "r"(b[1]));
}
__device__ __forceinline__ void cpa16(uint32_t dst, const void* src) {
    asm volatile("cp.async.cg.shared.global [%0], [%1], 16;" :: "r"(dst), "l"(src));
}
#define CPA_COMMIT() asm volatile("cp.async.commit_group;" ::: "memory")
#define CPA_WAIT(n)  asm volatile("cp.async.wait_group %0;" :: "n"(n) : "memory")

// ------------------- smem layout (dynamic) -------------------
#define QB0_O  0          // 65536 : Q buffer 0 (16 warps x 4KB slices)
#define QB1_O  65536      // 65536 : Q buffer 1
#define BH_O   131072     // 32768 : Bt hi [256 k][64 n] bf16 SW128
#define BL_O   163840     // 32768 : Bt lo
#define PART_O 196608     // 4096  : [16 w][64 c]
#define GMX_O  200704     // 256
#define GINV_O 200960     // 256
#define VR_O   201216     // 256   : [2 skl][32 e]
#define SMEM_SZ 201728

// ------------------- prep: A = I + Wl ; zero vs -------------------
__global__ void prep_kernel(const float* __restrict__ Wl) {
    int i = blockIdx.x * 256 + threadIdx.x;
    if (i < DD * DD) {
        int d = i >> 8, e = i & 255;
        g_A[i] = Wl[i] + (d == e ? 1.0f : 0.0f);
    }
    if (i < SQ * DD) g_vs[i] = 0.0f;
}

// ------------------- fused residual for k/q/v (2 rows/CTA) -------------------
__global__ void resid3_kernel(const float* __restrict__ key, const float* __restrict__ query,
                              const float* __restrict__ value,
                              const float* __restrict__ Wk, const float* __restrict__ bk,
                              const float* __restrict__ Wq, const float* __restrict__ bq,
                              const float* __restrict__ Wva, const float* __restrict__ bva) {
    const int which = blockIdx.y;
    const float* X = which == 0 ? key : which == 1 ? query : value;
    const float* W = which == 0 ? Wk  : which == 1 ? Wq    : Wva;
    const float* b = which == 0 ? bk  : which == 1 ? bq    : bva;

    __shared__ float Xs[2][DD];
    const int tid = threadIdx.x;           // output column d
    const int r0 = blockIdx.x * 2;
    #pragma unroll
    for (int r = 0; r < 2; r++) Xs[r][tid] = X[(r0 + r) * DD + tid];
    __syncthreads();

    float acc[2];
    const float bv = b[tid];
    #pragma unroll
    for (int r = 0; r < 2; r++) acc[r] = Xs[r][tid] + bv;

    for (int d0 = 0; d0 < DD; d0 += 8) {
        float w[8];
        #pragma unroll
        for (int j = 0; j < 8; j++) w[j] = W[(d0 + j) * DD + tid];
        #pragma unroll
        for (int r = 0; r < 2; r++) {
            float4 x0 = *reinterpret_cast<const float4*>(&Xs[r][d0]);
            float4 x1 = *reinterpret_cast<const float4*>(&Xs[r][d0 + 4]);
            acc[r] += x0.x * w[0] + x0.y * w[1] + x0.z * w[2] + x0.w * w[3]
                    + x1.x * w[4] + x1.y * w[5] + x1.z * w[6] + x1.w * w[7];
        }
    }

    if (which == 0) {
        #pragma unroll
        for (int r = 0; r < 2; r++) g_Kp[(r0 + r) * DD + tid] = acc[r];
    } else if (which == 2) {
        #pragma unroll
        for (int r = 0; r < 2; r++) g_Vp[(r0 + r) * DD + tid] = acc[r];
    } else {
        #pragma unroll
        for (int r = 0; r < 2; r++) {
            int sq = r0 + r;
            int kc = tid >> 6, kr = tid & 63;
            uint32_t off = (uint32_t)kc * 65536u + SWZ((uint32_t)(sq * 128 + kr * 2));
            __nv_bfloat16 h = __float2bfloat16(acc[r]);
            float lo = acc[r] - __bfloat162float(h);
            *reinterpret_cast<__nv_bfloat16*>(g_Qhi + off) = h;
            *reinterpret_cast<__nv_bfloat16*>(g_Qlo + off) = __float2bfloat16(lo);
        }
    }
}

// ------------------- final residual: out = vs + vs@Wvo + bvo -------------------
__global__ void resid_out_kernel(const float* __restrict__ W, const float* __restrict__ b,
                                 float* __restrict__ Y) {
    __shared__ float Xs[2][DD];
    const int tid = threadIdx.x;
    const int r0 = blockIdx.x * 2;
    #pragma unroll
    for (int r = 0; r < 2; r++) Xs[r][tid] = g_vs[(r0 + r) * DD + tid];
    __syncthreads();
    float acc[2];
    const float bv = b[tid];
    #pragma unroll
    for (int r = 0; r < 2; r++) acc[r] = Xs[r][tid] + bv;
    for (int d0 = 0; d0 < DD; d0 += 8) {
        float w[8];
        #pragma unroll
        for (int j = 0; j < 8; j++) w[j] = W[(d0 + j) * DD + tid];
        #pragma unroll
        for (int r = 0; r < 2; r++) {
            float4 x0 = *reinterpret_cast<const float4*>(&Xs[r][d0]);
            float4 x1 = *reinterpret_cast<const float4*>(&Xs[r][d0 + 4]);
            acc[r] += x0.x * w[0] + x0.y * w[1] + x0.z * w[2] + x0.w * w[3]
                    + x1.x * w[4] + x1.y * w[5] + x1.z * w[6] + x1.w * w[7];
        }
    }
    #pragma unroll
    for (int r = 0; r < 2; r++) Y[(r0 + r) * DD + tid] = acc[r];
}

// ------------------- MMA passes (per-warp Q slice: 32 rows x 64 k) -------------------
// hi chunk: A fragments loaded once, applied to both BH and BL
__device__ __forceinline__ void mma_hi(float (*acc)[8][4], uint32_t qs, uint32_t bh,
                                       uint32_t bl2, int kc, int L) {
    #pragma unroll
    for (int ks = 0; ks < 4; ks++) {
        uint32_t af[2][4];
        #pragma unroll
        for (int mi = 0; mi < 2; mi++) {
            int rl = mi * 16 + (L & 15);   // row within warp's 32-row slice
            uint32_t off = (uint32_t)(rl * 128) + ((uint32_t)((ks * 2 + (L >> 4)) * 16) ^ (uint32_t)((rl & 7) * 16));
            ldsm_x4(af[mi], qs + off);
        }
        int brow = kc * 64 + ks * 16 + (L & 15);
        uint32_t bxor = (uint32_t)((brow & 7) * 16);
        #pragma unroll
        for (int h = 0; h < 2; h++) {
            uint32_t bf[8];
            #pragma unroll
            for (int qq = 0; qq < 2; qq++) {
                uint32_t unit = (uint32_t)(h * 4 + qq * 2 + (L >> 4));
                ldsm_x4_t(bf + qq * 4, bh + (uint32_t)(brow * 128) + ((unit * 16) ^ bxor));
            }
            #pragma unroll
            for (int mi = 0; mi < 2; mi++)
                #pragma unroll
                for (int nj = 0; nj < 4; nj++)
                    mma_bf16(acc[mi][h * 4 + nj], af[mi], &bf[nj * 2]);
            #pragma unroll
            for (int qq = 0; qq < 2; qq++) {
                uint32_t unit = (uint32_t)(h * 4 + qq * 2 + (L >> 4));
                ldsm_x4_t(bf + qq * 4, bl2 + (uint32_t)(brow * 128) + ((unit * 16) ^ bxor));
            }
            #pragma unroll
            for (int mi = 0; mi < 2; mi++)
                #pragma unroll
                for (int nj = 0; nj < 4; nj++)
                    mma_bf16(acc[mi][h * 4 + nj], af[mi], &bf[nj * 2]);
        }
    }
}
// lo chunk: single pass vs BH
__device__ __forceinline__ void mma_lo(float (*acc)[8][4], uint32_t qs, uint32_t bh,
                                       int kc, int L) {
    #pragma unroll
    for (int ks = 0; ks < 4; ks++) {
        uint32_t af[2][4];
        #pragma unroll
        for (int mi = 0; mi < 2; mi++) {
            int rl = mi * 16 + (L & 15);
            uint32_t off = (uint32_t)(rl * 128) + ((uint32_t)((ks * 2 + (L >> 4)) * 16) ^ (uint32_t)((rl & 7) * 16));
            ldsm_x4(af[mi], qs + off);
        }
        int brow = kc * 64 + ks * 16 + (L & 15);
        uint32_t bxor = (uint32_t)((brow & 7) * 16);
        #pragma unroll
        for (int h = 0; h < 2; h++) {
            uint32_t bf[8];
            #pragma unroll
            for (int qq = 0; qq < 2; qq++) {
                uint32_t unit = (uint32_t)(h * 4 + qq * 2 + (L >> 4));
                ldsm_x4_t(bf + qq * 4, bh + (uint32_t)(brow * 128) + ((unit * 16) ^ bxor));
            }
            #pragma unroll
            for (int mi = 0; mi < 2; mi++)
                #pragma unroll
                for (int nj = 0; nj < 4; nj++)
                    mma_bf16(acc[mi][h * 4 + nj], af[mi], &bf[nj * 2]);
        }
    }
}

// per-warp Q slice prefetch: global chunk index g (0..127), c = g&7
__device__ __forceinline__ void issue_chunk(uint32_t smb, int g, int w, int L) {
    int c = g & 7;
    const uint8_t* src = ((c & 1) ? g_Qlo : g_Qhi) + (c >> 1) * 65536 + w * 32 * 128;
    uint32_t dst = smb + ((c & 1) ? QB1_O : QB0_O) + w * 4096;
    #pragma unroll
    for (int j = 0; j < 8; j++) {
        uint32_t off = (uint32_t)(L + j * 32) * 16u;
        cpa16(dst + off, src + off);
    }
    CPA_COMMIT();
}

// ------------------- main fused kernel -------------------
__global__ void __launch_bounds__(512, 1)
attn_main_kernel(const float* __restrict__ bl) {
    extern __shared__ __align__(128) uint8_t sm[];
    const uint32_t smb = smem_u32(sm);
    const int tid = threadIdx.x, L = tid & 31, w = tid >> 5;
    const int e0 = blockIdx.x * 32, skb = blockIdx.y * 32;

    float* PART = (float*)(sm + PART_O);
    float* GMX  = (float*)(sm + GMX_O);
    float* GINV = (float*)(sm + GINV_O);
    float* VR   = (float*)(sm + VR_O);

    float blv[8];
    #pragma unroll
    for (int j = 0; j < 8; j++)
        blv[j] = bl[e0 + (j >> 1) * 8 + (L & 3) * 2 + (j & 1)];

    float vs[32];
    #pragma unroll
    for (int i = 0; i < 32; i++) vs[i] = 0.0f;

    // prologue: per-warp prefetch of chunks 0,1
    issue_chunk(smb, 0, w, L);
    issue_chunk(smb, 1, w, L);

    #pragma unroll 1
    for (int rnd = 0; rnd < 16; rnd++) {
        const int sk0 = skb + rnd * 2;
        __syncthreads();   // prior round's BH/BL/VR consumers done

        // ---- build Bt[d][n] hi/lo : n = skl*32 + e_local ----
        #pragma unroll
        for (int i = 0; i < 4; i++) {
            int u = tid + i * 512;
            int d = u >> 3, g = u & 7;
            int skl = g >> 2;
            const float4* ap = (const float4*)(g_A + d * DD + e0 + (g & 3) * 8);
            float kv = g_Kp[(sk0 + skl) * DD + d];
            float4 a0 = ap[0], a1 = ap[1];
            float p[8] = { kv*a0.x, kv*a0.y, kv*a0.z, kv*a0.w,
                           kv*a1.x, kv*a1.y, kv*a1.z, kv*a1.w };
            uint32_t H[4], Lo[4];
            #pragma unroll
            for (int j = 0; j < 4; j++) {
                __nv_bfloat16 h0 = __float2bfloat16(p[2*j]);
                __nv_bfloat16 h1 = __float2bfloat16(p[2*j+1]);
                __nv_bfloat16 l0 = __float2bfloat16(p[2*j]   - __bfloat162float(h0));
                __nv_bfloat16 l1 = __float2bfloat16(p[2*j+1] - __bfloat162float(h1));
                H[j]  = (uint32_t)__bfloat16_as_ushort(h0) | ((uint32_t)__bfloat16_as_ushort(h1) << 16);
                Lo[j] = (uint32_t)__bfloat16_as_ushort(l0) | ((uint32_t)__bfloat16_as_ushort(l1) << 16);
            }
            uint32_t off = (uint32_t)(d * 128 + ((g ^ (d & 7)) * 16));
            *(uint4*)(sm + BH_O + off) = make_uint4(H[0], H[1], H[2], H[3]);
            *(uint4*)(sm + BL_O + off) = make_uint4(Lo[0], Lo[1], Lo[2], Lo[3]);
        }
        if (tid < 64) VR[tid] = g_Vp[(sk0 + (tid >> 5)) * DD + e0 + (tid & 31)];
        __syncthreads();   // B tiles + VR ready for all warps

        float acc[2][8][4];
        #pragma unroll
        for (int mi = 0; mi < 2; mi++)
            #pragma unroll
            for (int ni = 0; ni < 8; ni++)
                #pragma unroll
                for (int c = 0; c < 4; c++) acc[mi][ni][c] = 0.0f;

        // ---- barrier-free per-warp pipelined chunk loop ----
        #pragma unroll 1
        for (int c = 0; c < 8; c++) {
            const int g = rnd * 8 + c;
            if (g == 127) { CPA_WAIT(0); } else { CPA_WAIT(1); }

            uint32_t qs = smb + ((c & 1) ? QB1_O : QB0_O) + w * 4096;
            int kc = c >> 1;
            if ((c & 1) == 0) mma_hi(acc, qs, smb + BH_O, smb + BL_O, kc, L);
            else              mma_lo(acc, qs, smb + BH_O, kc, L);

            if (g + 2 <= 127) issue_chunk(smb, (g + 2) & 7, w, L);
        }

        // ---- epilogue: + bl, column swishmax over sq, vsum ----
        #pragma unroll
        for (int mi = 0; mi < 2; mi++)
            #pragma unroll
            for (int ni = 0; ni < 8; ni++)
                #pragma unroll
                for (int p = 0; p < 2; p++) {
                    float bv = blv[(ni & 3) * 2 + p];
                    acc[mi][ni][p]     += bv;
                    acc[mi][ni][p + 2] += bv;
                }

        float cm[16];
        #pragma unroll
        for (int ni = 0; ni < 8; ni++)
            #pragma unroll
            for (int p = 0; p < 2; p++)
                cm[ni * 2 + p] = fmaxf(fmaxf(acc[0][ni][p], acc[0][ni][p + 2]),
                                       fmaxf(acc[1][ni][p], acc[1][ni][p + 2]));
        #pragma unroll
        for (int off = 4; off <= 16; off <<= 1)
            #pragma unroll
            for (int i = 0; i < 16; i++)
                cm[i] = fmaxf(cm[i], __shfl_xor_sync(0xffffffffu, cm[i], off));
        if (L < 4)
            #pragma unroll
            for (int i = 0; i < 16; i++)
                PART[w * 64 + (i >> 1) * 8 + L * 2 + (i & 1)] = cm[i];
        __syncthreads();
        if (tid < 64) {
            float m = PART[tid];
            #pragma unroll
            for (int w2 = 1; w2 < 16; w2++) m = fmaxf(m, PART[w2 * 64 + tid]);
            GMX[tid] = m;
        }
        __syncthreads();

        float gm[16];
        #pragma unroll
        for (int i = 0; i < 16; i++)
            gm[i] = GMX[(i >> 1) * 8 + (L & 3) * 2 + (i & 1)];
        #pragma unroll
        for (int mi = 0; mi < 2; mi++)
            #pragma unroll
            for (int ni = 0; ni < 8; ni++)
                #pragma unroll
                for (int p = 0; p < 2; p++) {
                    float g = gm[ni * 2 + p];
                    float a0 = acc[mi][ni][p],     a1 = acc[mi][ni][p + 2];
                    acc[mi][ni][p]     = a0 * __expf(a0 - g);
                    acc[mi][ni][p + 2] = a1 * __expf(a1 - g);
                }

        float cs[16];
        #pragma unroll
        for (int ni = 0; ni < 8; ni++)
            #pragma unroll
            for (int p = 0; p < 2; p++)
                cs[ni * 2 + p] = fabsf(acc[0][ni][p]) + fabsf(acc[0][ni][p + 2])
                               + fabsf(acc[1][ni][p]) + fabsf(acc[1][ni][p + 2]);
        #pragma unroll
        for (int off = 4; off <= 16; off <<= 1)
            #pragma unroll
            for (int i = 0; i < 16; i++)
                cs[i] += __shfl_xor_sync(0xffffffffu, cs[i], off);
        if (L < 4)
            #pragma unroll
            for (int i = 0; i < 16; i++)
                PART[w * 64 + (i >> 1) * 8 + L * 2 + (i & 1)] = cs[i];
        __syncthreads();
        if (tid < 64) {
            float s = PART[tid];
            #pragma unroll
            for (int w2 = 1; w2 < 16; w2++) s += PART[w2 * 64 + tid];
            GINV[tid] = 1.0f / (s + 1.0f);   // NOT_EPSILON = 1.0
        }
        __syncthreads();

        float gv[16];
        #pragma unroll
        for (int i = 0; i < 16; i++) {
            int cidx = (i >> 1) * 8 + (L & 3) * 2 + (i & 1);
            int eL = ((i >> 1) & 3) * 8 + (L & 3) * 2 + (i & 1);
            gv[i] = GINV[cidx] * VR[(i >= 8 ? 32 : 0) + eL];
        }
        #pragma unroll
        for (int mi = 0; mi < 2; mi++)
            #pragma unroll
            for (int ni = 0; ni < 8; ni++)
                #pragma unroll
                for (int p = 0; p < 2; p++) {
                    float f = gv[ni * 2 + p];
                    int j = (ni & 3) * 2 + p;
                    vs[(mi * 2 + 0) * 8 + j] += acc[mi][ni][p]     * f;
                    vs[(mi * 2 + 1) * 8 + j] += acc[mi][ni][p + 2] * f;
                }
    }

    // ---- write vsum (accumulate across 16 sk-group CTAs) ----
    #pragma unroll
    for (int mi = 0; mi < 2; mi++)
        #pragma unroll
        for (int rh = 0; rh < 2; rh++)
            #pragma unroll
            for (int j = 0; j < 8; j++) {
                int m = w * 32 + mi * 16 + rh * 8 + (L >> 2);
                int e = e0 + (j >> 1) * 8 + (L & 3) * 2 + (j & 1);
                atomicAdd(&g_vs[m * DD + e], vs[(mi * 2 + rh) * 8 + j]);
            }
}

// ---------------------------------------------------------------------------
extern "C" void kernel_launch(void* const* d_in, const int* in_sizes, int n_in,
                              void* d_out, int out_size) {
    const float* query = (const float*)d_in[0];
    const float* key   = (const float*)d_in[1];
    const float* value = (const float*)d_in[2];
    const float* Wk    = (const float*)d_in[3];
    const float* bk    = (const float*)d_in[4];
    const float* Wq    = (const float*)d_in[5];
    const float* bq    = (const float*)d_in[6];
    const float* Wva   = (const float*)d_in[7];
    const float* bva   = (const float*)d_in[8];
    const float* Wl    = (const float*)d_in[9];
    const float* bl    = (const float*)d_in[10];
    const float* Wvo   = (const float*)d_in[11];
    const float* bvo   = (const float*)d_in[12];
    float* out = (float*)d_out;

    cudaFuncSetAttribute(attn_main_kernel, cudaFuncAttributeMaxDynamicSharedMemorySize, SMEM_SZ);

    prep_kernel<<<512, 256>>>(Wl);
    resid3_kernel<<<dim3(256, 3), 256>>>(key, query, value, Wk, bk, Wq, bq, Wva, bva);
    attn_main_kernel<<<dim3(8, 16), 512, SMEM_SZ>>>(bl);
    resid_out_kernel<<<256, 256>>>(Wvo, bvo, out);
}